// round 14
// baseline (speedup 1.0000x reference)
#include <cuda_runtime.h>
#include <cuda_bf16.h>
#include <math.h>
#include <stdint.h>

#define NN 50000
#define EE 800000
#define BG 512
#define D  128
#define SCAN_BLKS 49   // ceil(50000 / 1024)

// ---------------- scratch (static device globals; no allocation) ----------------
__device__ int   g_deg[NN];
__device__ int   g_rowptr[NN + 1];
__device__ int   g_cursor[NN];
__device__ int   g_col[EE];
__device__ int   g_root[BG + 1];
__device__ int   g_bsum[SCAN_BLKS];
__device__ int   g_boff[SCAN_BLKS];
__device__ int   g_scnt;
__device__ int   g_sgo;
__device__ float g_mean[NN * D];
__device__ float g_part[NN * D];
__device__ float g_h1[NN * D];
__device__ float g_h2[NN * D];
// W in per-thread mma-fragment layout: [layer][k_step 16][n_atom 16][lane 32]
__device__ uint4 g_Wfrag[3 * 16 * 16 * 32];

// ---------------- fused init: zero deg, roots, scan flags, W fragment prep ----------------
__global__ void k_initprep(const int* __restrict__ batch,
                           const float* __restrict__ Wl1, const float* __restrict__ Wr1,
                           const float* __restrict__ Wl2, const float* __restrict__ Wr2,
                           const float* __restrict__ Wl3, const float* __restrict__ Wr3) {
    int i = blockIdx.x * blockDim.x + threadIdx.x;
    if (i < NN) {
        g_deg[i] = 0;
        int b = batch[i];
        if (i == 0 || batch[i - 1] != b) g_root[b] = i;
        if (i == 0) { g_root[BG] = NN; g_scnt = 0; g_sgo = 0; }
    }
    if (i < 3 * 16 * 16 * 32) {
        int L    = i >> 13;
        int rem  = i & 8191;
        int t    = rem >> 9;
        int na   = (rem >> 5) & 15;
        int lane = rem & 31;
        const float* Wl = (L == 0) ? Wl1 : (L == 1) ? Wl2 : Wl3;
        const float* Wr = (L == 0) ? Wr1 : (L == 1) ? Wr2 : Wr3;
        int n  = na * 8 + (lane >> 2);
        int k0 = t * 16 + (lane & 3) * 2;
        float w[4];
#pragma unroll
        for (int q = 0; q < 4; q++) {
            int k = k0 + (q >> 1) * 8 + (q & 1);
            w[q] = (k < 128) ? Wl[k * 128 + n] : Wr[(k - 128) * 128 + n];
        }
        unsigned short h[4], l[4];
#pragma unroll
        for (int q = 0; q < 4; q++) {
            __nv_bfloat16 hb = __float2bfloat16(w[q]);
            __nv_bfloat16 lb = __float2bfloat16(w[q] - __bfloat162float(hb));
            h[q] = __bfloat16_as_ushort(hb);
            l[q] = __bfloat16_as_ushort(lb);
        }
        uint4 v;
        v.x = (uint32_t)h[0] | ((uint32_t)h[1] << 16);
        v.y = (uint32_t)h[2] | ((uint32_t)h[3] << 16);
        v.z = (uint32_t)l[0] | ((uint32_t)l[1] << 16);
        v.w = (uint32_t)l[2] | ((uint32_t)l[3] << 16);
        g_Wfrag[i] = v;
    }
}

__global__ void k_hist(const int* __restrict__ dst) {
    int e = blockIdx.x * blockDim.x + threadIdx.x;
    if (e < EE) atomicAdd(&g_deg[dst[e]], 1);
}

// ---------------- single-kernel scan ----------------
__global__ void k_scan_one() {
    __shared__ int sc[1024];
    __shared__ int s_last;
    __shared__ int s_boff;
    __shared__ int tops[64];
    int t = threadIdx.x;
    int bid = blockIdx.x;
    int i = bid * 1024 + t;
    int d = (i < NN) ? g_deg[i] : 0;
    sc[t] = d;
    __syncthreads();
#pragma unroll
    for (int off = 1; off < 1024; off <<= 1) {
        int add = (t >= off) ? sc[t - off] : 0;
        __syncthreads();
        sc[t] += add;
        __syncthreads();
    }
    int excl = sc[t] - d;
    if (t == 1023) g_bsum[bid] = sc[1023];
    __syncthreads();
    if (t == 0) {
        __threadfence();
        int a = atomicAdd(&g_scnt, 1);
        s_last = (a == SCAN_BLKS - 1) ? 1 : 0;
    }
    __syncthreads();
    if (s_last) {
        if (t < 64) tops[t] = (t < SCAN_BLKS) ? *(volatile int*)&g_bsum[t] : 0;
        __syncthreads();
#pragma unroll
        for (int off = 1; off < 64; off <<= 1) {
            int add = (t < 64 && t >= off) ? tops[t - off] : 0;
            __syncthreads();
            if (t < 64) tops[t] += add;
            __syncthreads();
        }
        if (t < SCAN_BLKS) g_boff[t] = tops[t] - *(volatile int*)&g_bsum[t];
        if (t == SCAN_BLKS - 1) g_rowptr[NN] = tops[t];
        __syncthreads();
        if (t == 0) {
            __threadfence();
            atomicExch(&g_sgo, 1);
        }
    }
    if (t == 0) {
        while (atomicAdd(&g_sgo, 0) == 0) { }
        s_boff = *(volatile int*)&g_boff[bid];
    }
    __syncthreads();
    if (i < NN) {
        int v = excl + s_boff;
        g_rowptr[i] = v;
        g_cursor[i] = v;
    }
}

__global__ void k_fill(const int* __restrict__ src, const int* __restrict__ dst) {
    int e = blockIdx.x * blockDim.x + threadIdx.x;
    if (e < EE) {
        int d = dst[e];
        int p = atomicAdd(&g_cursor[d], 1);
        g_col[p] = src[e];
    }
}

// ---------------- mean aggregation: warp per node, lane = one float4, 4-way unroll ----------------
__global__ void k_aggregate(const float* __restrict__ feat, float* __restrict__ mean) {
    int warp = (blockIdx.x * blockDim.x + threadIdx.x) >> 5;
    int lane = threadIdx.x & 31;
    if (warp >= NN) return;
    int s = g_rowptr[warp];
    int e = g_rowptr[warp + 1];
    float4 acc = make_float4(0.f, 0.f, 0.f, 0.f);
    const float4* f4 = (const float4*)feat;
    int i = s;
    for (; i + 4 <= e; i += 4) {
        int c0 = __ldg(&g_col[i]);
        int c1 = __ldg(&g_col[i + 1]);
        int c2 = __ldg(&g_col[i + 2]);
        int c3 = __ldg(&g_col[i + 3]);
        float4 v0 = __ldg(&f4[c0 * 32 + lane]);
        float4 v1 = __ldg(&f4[c1 * 32 + lane]);
        float4 v2 = __ldg(&f4[c2 * 32 + lane]);
        float4 v3 = __ldg(&f4[c3 * 32 + lane]);
        acc.x += v0.x + v1.x + v2.x + v3.x;
        acc.y += v0.y + v1.y + v2.y + v3.y;
        acc.z += v0.z + v1.z + v2.z + v3.z;
        acc.w += v0.w + v1.w + v2.w + v3.w;
    }
    for (; i < e; i++) {
        int c = __ldg(&g_col[i]);
        float4 v = __ldg(&f4[c * 32 + lane]);
        acc.x += v.x; acc.y += v.y; acc.z += v.z; acc.w += v.w;
    }
    int cnt = e - s;
    float inv = 1.0f / (float)(cnt > 0 ? cnt : 1);
    acc.x *= inv; acc.y *= inv; acc.z *= inv; acc.w *= inv;
    ((float4*)mean)[warp * 32 + lane] = acc;
}

// ---------------- shared GEMM pieces ----------------
#define APITCH 36

__device__ __forceinline__ void mma_bf16(float* c, const uint32_t* a,
                                         uint32_t b0, uint32_t b1) {
    asm("mma.sync.aligned.m16n8k16.row.col.f32.bf16.bf16.f32 "
        "{%0,%1,%2,%3}, {%4,%5,%6,%7}, {%8,%9}, {%0,%1,%2,%3};"
        : "+f"(c[0]), "+f"(c[1]), "+f"(c[2]), "+f"(c[3])
        : "r"(a[0]), "r"(a[1]), "r"(a[2]), "r"(a[3]), "r"(b0), "r"(b1));
}

// Stage one 128x64 fp32 chunk as bf16 hi/lo smem images.
__device__ __forceinline__ void stage_chunk(const float* A, int row0, int kb,
                                            uint32_t* sAhi, uint32_t* sAlo, int tid) {
    int r = tid >> 1;
    int half = tid & 1;
    int grow = row0 + r;
    const float4* Ag = (const float4*)(A + (size_t)grow * D + kb);
#pragma unroll
    for (int q = 0; q < 8; q++) {
        float4 v = make_float4(0.f, 0.f, 0.f, 0.f);
        if (grow < NN) v = __ldg(&Ag[half * 8 + q]);
        __nv_bfloat16 hx = __float2bfloat16(v.x);
        __nv_bfloat16 hy = __float2bfloat16(v.y);
        __nv_bfloat16 hz = __float2bfloat16(v.z);
        __nv_bfloat16 hw = __float2bfloat16(v.w);
        uint2 hv, lv;
        hv.x = (uint32_t)__bfloat16_as_ushort(hx) | ((uint32_t)__bfloat16_as_ushort(hy) << 16);
        hv.y = (uint32_t)__bfloat16_as_ushort(hz) | ((uint32_t)__bfloat16_as_ushort(hw) << 16);
        __nv_bfloat16 lx = __float2bfloat16(v.x - __bfloat162float(hx));
        __nv_bfloat16 ly = __float2bfloat16(v.y - __bfloat162float(hy));
        __nv_bfloat16 lz = __float2bfloat16(v.z - __bfloat162float(hz));
        __nv_bfloat16 lw = __float2bfloat16(v.w - __bfloat162float(hw));
        lv.x = (uint32_t)__bfloat16_as_ushort(lx) | ((uint32_t)__bfloat16_as_ushort(ly) << 16);
        lv.y = (uint32_t)__bfloat16_as_ushort(lz) | ((uint32_t)__bfloat16_as_ushort(lw) << 16);
        int c = half * 16 + q * 2;
        *(uint2*)&sAhi[r * APITCH + c] = hv;
        *(uint2*)&sAlo[r * APITCH + c] = lv;
    }
}

// mma over one staged chunk (4 k-steps), B fragments at absolute chunk index bchunk.
__device__ __forceinline__ void mma_chunk(const uint4* Wfrag, int bchunk,
                                          const uint32_t* sAhi, const uint32_t* sAlo,
                                          float acc[4][4][4], int wc, int rb, int lane) {
#pragma unroll
    for (int t = 0; t < 4; t++) {
        uint4 B[4];
#pragma unroll
        for (int j = 0; j < 4; j++)
            B[j] = __ldg(&Wfrag[(((bchunk * 4 + t) * 16) + (wc * 4 + j)) * 32 + lane]);
        const int cw = t * 8 + (lane & 3);
#pragma unroll
        for (int i = 0; i < 4; i++) {
            int base = (rb + i * 16) * APITCH;
            uint32_t ah[4], al[4];
            ah[0] = sAhi[base + cw];
            ah[1] = sAhi[base + 8 * APITCH + cw];
            ah[2] = sAhi[base + cw + 4];
            ah[3] = sAhi[base + 8 * APITCH + cw + 4];
            al[0] = sAlo[base + cw];
            al[1] = sAlo[base + 8 * APITCH + cw];
            al[2] = sAlo[base + cw + 4];
            al[3] = sAlo[base + 8 * APITCH + cw + 4];
#pragma unroll
            for (int j = 0; j < 4; j++) {
                mma_bf16(acc[i][j], ah, B[j].x, B[j].y);
                mma_bf16(acc[i][j], ah, B[j].z, B[j].w);
                mma_bf16(acc[i][j], al, B[j].x, B[j].y);
            }
        }
    }
}

// ---------------- partial GEMM: part = feat @ Wr (chunks 2,3) ----------------
__global__ __launch_bounds__(256)
void k_gemm_part(const float* __restrict__ feat, const uint4* __restrict__ Wfrag,
                 float* __restrict__ part) {
    __shared__ uint32_t sAhi[128 * APITCH];
    __shared__ uint32_t sAlo[128 * APITCH];
    const int tid  = threadIdx.x;
    const int wid  = tid >> 5;
    const int lane = tid & 31;
    const int wr = wid >> 2;
    const int wc = wid & 3;
    const int row0 = blockIdx.x * 128;
    const int rb = wr * 64 + (lane >> 2);

    float acc[4][4][4];
#pragma unroll
    for (int i = 0; i < 4; i++)
#pragma unroll
        for (int j = 0; j < 4; j++)
#pragma unroll
            for (int r = 0; r < 4; r++) acc[i][j][r] = 0.f;

#pragma unroll
    for (int h = 0; h < 2; h++) {
        stage_chunk(feat, row0, h * 64, sAhi, sAlo, tid);
        __syncthreads();
        mma_chunk(Wfrag, 2 + h, sAhi, sAlo, acc, wc, rb, lane);
        __syncthreads();
    }

#pragma unroll
    for (int j = 0; j < 4; j++) {
        int col = wc * 32 + j * 8 + (lane & 3) * 2;
#pragma unroll
        for (int i = 0; i < 4; i++) {
            int row = row0 + wr * 64 + i * 16 + (lane >> 2);
            if (row < NN)
                *(float2*)(part + (size_t)row * D + col) =
                    make_float2(acc[i][j][0], acc[i][j][1]);
            if (row + 8 < NN)
                *(float2*)(part + (size_t)(row + 8) * D + col) =
                    make_float2(acc[i][j][2], acc[i][j][3]);
        }
    }
}

// ---------------- main GEMM: out = relu(mean @ Wl + part + bias) (chunks 0,1) ----------------
__global__ __launch_bounds__(256)
void k_gemm_main(const float* __restrict__ mean, const uint4* __restrict__ Wfrag,
                 const float* __restrict__ part, const float* __restrict__ bias,
                 float* __restrict__ out) {
    __shared__ uint32_t sAhi[128 * APITCH];
    __shared__ uint32_t sAlo[128 * APITCH];
    const int tid  = threadIdx.x;
    const int wid  = tid >> 5;
    const int lane = tid & 31;
    const int wr = wid >> 2;
    const int wc = wid & 3;
    const int row0 = blockIdx.x * 128;
    const int rb = wr * 64 + (lane >> 2);

    float acc[4][4][4];
#pragma unroll
    for (int i = 0; i < 4; i++)
#pragma unroll
        for (int j = 0; j < 4; j++)
#pragma unroll
            for (int r = 0; r < 4; r++) acc[i][j][r] = 0.f;

#pragma unroll
    for (int h = 0; h < 2; h++) {
        stage_chunk(mean, row0, h * 64, sAhi, sAlo, tid);
        __syncthreads();
        mma_chunk(Wfrag, h, sAhi, sAlo, acc, wc, rb, lane);
        __syncthreads();
    }

#pragma unroll
    for (int j = 0; j < 4; j++) {
        int col = wc * 32 + j * 8 + (lane & 3) * 2;
        float b0 = __ldg(&bias[col]);
        float b1 = __ldg(&bias[col + 1]);
#pragma unroll
        for (int i = 0; i < 4; i++) {
            int row = row0 + wr * 64 + i * 16 + (lane >> 2);
            if (row < NN) {
                float2 p = *(const float2*)(part + (size_t)row * D + col);
                float2 v0;
                v0.x = fmaxf(acc[i][j][0] + p.x + b0, 0.f);
                v0.y = fmaxf(acc[i][j][1] + p.y + b1, 0.f);
                *(float2*)(out + (size_t)row * D + col) = v0;
            }
            if (row + 8 < NN) {
                float2 p = *(const float2*)(part + (size_t)(row + 8) * D + col);
                float2 v1;
                v1.x = fmaxf(acc[i][j][2] + p.x + b0, 0.f);
                v1.y = fmaxf(acc[i][j][3] + p.y + b1, 0.f);
                *(float2*)(out + (size_t)(row + 8) * D + col) = v1;
            }
        }
    }
}

// ---------------- fully fused tail: max-pool -> mlp1 -> mlp2 -> head ----------------
__global__ void k_tail(const float* __restrict__ h, const float* __restrict__ x,
                       const float* __restrict__ W1, const float* __restrict__ b1,
                       const float* __restrict__ W2, const float* __restrict__ b2,
                       const float* __restrict__ Wsm, const float* __restrict__ bsm,
                       const float* __restrict__ Wnews, const float* __restrict__ bnews,
                       const float* __restrict__ Wcat, const float* __restrict__ bcat,
                       float* __restrict__ out) {
    __shared__ float pool[128];
    __shared__ float pmax[256];
    __shared__ float f1s[256];
    __shared__ float f2s[128];
    __shared__ float xroot[128];
    int g = blockIdx.x;
    int tid = threadIdx.x;
    int col = tid & 127, half = tid >> 7;
    int s = g_root[g], e = g_root[g + 1];
    float m = -3.4e38f;
    for (int n = s + half; n < e; n += 2) m = fmaxf(m, h[(size_t)n * D + col]);
    pmax[tid] = m;
    __syncthreads();
    if (tid < 128) {
        pool[tid] = fmaxf(pmax[tid], pmax[tid + 128]);
        xroot[tid] = x[(size_t)s * D + tid];
    }
    __syncthreads();
    float a1 = b1[tid];
#pragma unroll 16
    for (int k = 0; k < 128; k++) a1 += pool[k] * W1[k * 256 + tid];
    f1s[tid] = fmaxf(a1, 0.f);
    __syncthreads();
    if (tid < 128) {
        float a2 = b2[tid];
#pragma unroll 16
        for (int k = 0; k < 256; k++) a2 += f1s[k] * W2[k * 128 + tid];
        f2s[tid] = fmaxf(a2, 0.f);
    }
    __syncthreads();
    if (tid < 32) {
        int kb = tid * 4;
        float s0 = 0.f, s1 = 0.f, n0 = 0.f, n1 = 0.f;
#pragma unroll
        for (int t = 0; t < 4; t++) {
            float fv = f2s[kb + t];
            float xv = xroot[kb + t];
            s0 += fv * Wsm[(kb + t) * 2 + 0];
            s1 += fv * Wsm[(kb + t) * 2 + 1];
            n0 += xv * Wnews[(kb + t) * 2 + 0];
            n1 += xv * Wnews[(kb + t) * 2 + 1];
        }
#pragma unroll
        for (int off = 16; off > 0; off >>= 1) {
            s0 += __shfl_down_sync(0xffffffffu, s0, off);
            s1 += __shfl_down_sync(0xffffffffu, s1, off);
            n0 += __shfl_down_sync(0xffffffffu, n0, off);
            n1 += __shfl_down_sync(0xffffffffu, n1, off);
        }
        if (tid == 0) {
            float h0 = fmaxf(s0 + bsm[0], 0.f);
            float h1 = fmaxf(s1 + bsm[1], 0.f);
            float m0 = fmaxf(n0 + bnews[0], 0.f);
            float m1 = fmaxf(n1 + bnews[1], 0.f);
            float z = h0 * Wcat[0] + h1 * Wcat[1] + m0 * Wcat[2] + m1 * Wcat[3] + bcat[0];
            out[g] = 1.0f / (1.0f + expf(-z));
        }
    }
}

// ---------------- launch (stream fork/join, capture-safe) ----------------
static cudaStream_t s_sB = 0;
static cudaEvent_t  s_eI = 0, s_eP0 = 0, s_eP1 = 0, s_eP2 = 0, s_eM0 = 0, s_eM1 = 0;
static int s_ready = 0;

extern "C" void kernel_launch(void* const* d_in, const int* in_sizes, int n_in,
                              void* d_out, int out_size) {
    const float* x     = (const float*)d_in[0];
    const int*   ei    = (const int*)d_in[1];
    const int*   src   = ei;
    const int*   dst   = ei + EE;
    const int*   batch = (const int*)d_in[2];
    const float* Wl1 = (const float*)d_in[3];
    const float* Wr1 = (const float*)d_in[4];
    const float* bl1 = (const float*)d_in[5];
    const float* Wl2 = (const float*)d_in[6];
    const float* Wr2 = (const float*)d_in[7];
    const float* bl2 = (const float*)d_in[8];
    const float* Wl3 = (const float*)d_in[9];
    const float* Wr3 = (const float*)d_in[10];
    const float* bl3 = (const float*)d_in[11];
    const float* W_f1 = (const float*)d_in[12];
    const float* b_f1 = (const float*)d_in[13];
    const float* W_f2 = (const float*)d_in[14];
    const float* b_f2 = (const float*)d_in[15];
    const float* W_sm = (const float*)d_in[16];
    const float* b_sm = (const float*)d_in[17];
    const float* W_news = (const float*)d_in[18];
    const float* b_news = (const float*)d_in[19];
    const float* W_cat = (const float*)d_in[20];
    const float* b_cat = (const float*)d_in[21];
    float* out = (float*)d_out;

    float *mean, *part, *h1, *h2;
    uint4* wfrag;
    cudaGetSymbolAddress((void**)&mean, g_mean);
    cudaGetSymbolAddress((void**)&part, g_part);
    cudaGetSymbolAddress((void**)&h1, g_h1);
    cudaGetSymbolAddress((void**)&h2, g_h2);
    cudaGetSymbolAddress((void**)&wfrag, g_Wfrag);

    if (!s_ready) {
        if (cudaStreamCreateWithFlags(&s_sB, cudaStreamNonBlocking) != cudaSuccess)
            s_sB = 0;
        cudaEventCreateWithFlags(&s_eI,  cudaEventDisableTiming);
        cudaEventCreateWithFlags(&s_eP0, cudaEventDisableTiming);
        cudaEventCreateWithFlags(&s_eP1, cudaEventDisableTiming);
        cudaEventCreateWithFlags(&s_eP2, cudaEventDisableTiming);
        cudaEventCreateWithFlags(&s_eM0, cudaEventDisableTiming);
        cudaEventCreateWithFlags(&s_eM1, cudaEventDisableTiming);
        s_ready = 1;
    }
    cudaStream_t sB = s_sB;   // 0 => everything serial on default stream (fallback)

    const int TB = 256;
    const int gN = (NN + TB - 1) / TB;
    const int gE = (EE + TB - 1) / TB;
    const int gAgg = (NN * 32 + TB - 1) / TB;
    const int gGemm = (NN + 127) / 128;

    // init (roots + wfrag + deg zero)
    k_initprep<<<gN, TB>>>(batch, Wl1, Wr1, Wl2, Wr2, Wl3, Wr3);
    cudaEventRecord(s_eI, 0);

    // side stream: partial1 = x @ Wr1 (overlaps CSR build)
    cudaStreamWaitEvent(sB, s_eI, 0);
    k_gemm_part<<<gGemm, TB, 0, sB>>>(x, wfrag, part);
    cudaEventRecord(s_eP0, sB);

    // CSR build on main stream
    k_hist<<<gE, TB>>>(dst);
    k_scan_one<<<SCAN_BLKS, 1024>>>();
    k_fill<<<gE, TB>>>(src, dst);

    // layer 1
    k_aggregate<<<gAgg, TB>>>(x, mean);
    cudaStreamWaitEvent(0, s_eP0, 0);
    k_gemm_main<<<gGemm, TB>>>(mean, wfrag, part, bl1, h1);
    cudaEventRecord(s_eM0, 0);

    // layer 2 (partial2 overlaps agg2)
    cudaStreamWaitEvent(sB, s_eM0, 0);
    k_gemm_part<<<gGemm, TB, 0, sB>>>(h1, wfrag + 8192, part);
    cudaEventRecord(s_eP1, sB);
    k_aggregate<<<gAgg, TB>>>(h1, mean);
    cudaStreamWaitEvent(0, s_eP1, 0);
    k_gemm_main<<<gGemm, TB>>>(mean, wfrag + 8192, part, bl2, h2);
    cudaEventRecord(s_eM1, 0);

    // layer 3 (partial3 overlaps agg3)
    cudaStreamWaitEvent(sB, s_eM1, 0);
    k_gemm_part<<<gGemm, TB, 0, sB>>>(h2, wfrag + 16384, part);
    cudaEventRecord(s_eP2, sB);
    k_aggregate<<<gAgg, TB>>>(h2, mean);
    cudaStreamWaitEvent(0, s_eP2, 0);
    k_gemm_main<<<gGemm, TB>>>(mean, wfrag + 16384, part, bl3, h1);

    // fused tail
    k_tail<<<BG, TB>>>(h1, x, W_f1, b_f1, W_f2, b_f2, W_sm, b_sm,
                       W_news, b_news, W_cat, b_cat, out);
}

// round 15
// speedup vs baseline: 1.1349x; 1.1349x over previous
#include <cuda_runtime.h>
#include <cuda_bf16.h>
#include <math.h>
#include <stdint.h>

#define NN 50000
#define EE 800000
#define BG 512
#define D  128
#define SCAN_BLKS 49   // ceil(50000 / 1024)

// ---------------- scratch (static device globals; no allocation) ----------------
__device__ int      g_deg[NN];
__device__ int      g_rowptr[NN + 1];
__device__ int      g_cursor[NN];
__device__ int      g_col[EE];
__device__ int      g_root[BG + 1];
__device__ int      g_bsum[SCAN_BLKS];
__device__ int      g_boff[SCAN_BLKS];
__device__ int      g_scnt;
__device__ int      g_sgo;
__device__ uint32_t g_mean[NN * D];   // packed bf16 hi (low 16) | lo (high 16)
__device__ float    g_h1[NN * D];
__device__ float    g_h2[NN * D];
// W in per-thread mma-fragment layout: [layer][k_step 16][n_atom 16][lane 32]
// each uint4 = {bh0, bh1, bl0, bl1}
__device__ uint4 g_Wfrag[3 * 16 * 16 * 32];

// ---------------- fused init: zero deg, roots, scan flags, W fragment prep ----------------
__global__ void k_initprep(const int* __restrict__ batch,
                           const float* __restrict__ Wl1, const float* __restrict__ Wr1,
                           const float* __restrict__ Wl2, const float* __restrict__ Wr2,
                           const float* __restrict__ Wl3, const float* __restrict__ Wr3) {
    int i = blockIdx.x * blockDim.x + threadIdx.x;
    if (i < NN) {
        g_deg[i] = 0;
        int b = batch[i];
        if (i == 0 || batch[i - 1] != b) g_root[b] = i;
        if (i == 0) { g_root[BG] = NN; g_scnt = 0; g_sgo = 0; }
    }
    if (i < 3 * 16 * 16 * 32) {
        int L    = i >> 13;
        int rem  = i & 8191;
        int t    = rem >> 9;
        int na   = (rem >> 5) & 15;
        int lane = rem & 31;
        const float* Wl = (L == 0) ? Wl1 : (L == 1) ? Wl2 : Wl3;
        const float* Wr = (L == 0) ? Wr1 : (L == 1) ? Wr2 : Wr3;
        int n  = na * 8 + (lane >> 2);
        int k0 = t * 16 + (lane & 3) * 2;
        float w[4];
#pragma unroll
        for (int q = 0; q < 4; q++) {
            int k = k0 + (q >> 1) * 8 + (q & 1);
            w[q] = (k < 128) ? Wl[k * 128 + n] : Wr[(k - 128) * 128 + n];
        }
        unsigned short h[4], l[4];
#pragma unroll
        for (int q = 0; q < 4; q++) {
            __nv_bfloat16 hb = __float2bfloat16(w[q]);
            __nv_bfloat16 lb = __float2bfloat16(w[q] - __bfloat162float(hb));
            h[q] = __bfloat16_as_ushort(hb);
            l[q] = __bfloat16_as_ushort(lb);
        }
        uint4 v;
        v.x = (uint32_t)h[0] | ((uint32_t)h[1] << 16);
        v.y = (uint32_t)h[2] | ((uint32_t)h[3] << 16);
        v.z = (uint32_t)l[0] | ((uint32_t)l[1] << 16);
        v.w = (uint32_t)l[2] | ((uint32_t)l[3] << 16);
        g_Wfrag[i] = v;
    }
}

__global__ void k_hist(const int* __restrict__ dst) {
    int e = blockIdx.x * blockDim.x + threadIdx.x;
    if (e < EE) atomicAdd(&g_deg[dst[e]], 1);
}

// ---------------- single-kernel scan: local scans + resident global barrier ----------------
__global__ void k_scan_one() {
    __shared__ int sc[1024];
    __shared__ int s_last;
    __shared__ int s_boff;
    __shared__ int tops[64];
    int t = threadIdx.x;
    int bid = blockIdx.x;
    int i = bid * 1024 + t;
    int d = (i < NN) ? g_deg[i] : 0;
    sc[t] = d;
    __syncthreads();
#pragma unroll
    for (int off = 1; off < 1024; off <<= 1) {
        int add = (t >= off) ? sc[t - off] : 0;
        __syncthreads();
        sc[t] += add;
        __syncthreads();
    }
    int excl = sc[t] - d;
    if (t == 1023) g_bsum[bid] = sc[1023];
    __syncthreads();
    if (t == 0) {
        __threadfence();
        int a = atomicAdd(&g_scnt, 1);
        s_last = (a == SCAN_BLKS - 1) ? 1 : 0;
    }
    __syncthreads();
    if (s_last) {
        if (t < 64) tops[t] = (t < SCAN_BLKS) ? *(volatile int*)&g_bsum[t] : 0;
        __syncthreads();
#pragma unroll
        for (int off = 1; off < 64; off <<= 1) {
            int add = (t < 64 && t >= off) ? tops[t - off] : 0;
            __syncthreads();
            if (t < 64) tops[t] += add;
            __syncthreads();
        }
        if (t < SCAN_BLKS) g_boff[t] = tops[t] - *(volatile int*)&g_bsum[t];
        if (t == SCAN_BLKS - 1) g_rowptr[NN] = tops[t];
        __syncthreads();
        if (t == 0) {
            __threadfence();
            atomicExch(&g_sgo, 1);
        }
    }
    if (t == 0) {
        while (atomicAdd(&g_sgo, 0) == 0) { }
        s_boff = *(volatile int*)&g_boff[bid];
    }
    __syncthreads();
    if (i < NN) {
        int v = excl + s_boff;
        g_rowptr[i] = v;
        g_cursor[i] = v;
    }
}

__global__ void k_fill(const int* __restrict__ src, const int* __restrict__ dst) {
    int e = blockIdx.x * blockDim.x + threadIdx.x;
    if (e < EE) {
        int d = dst[e];
        int p = atomicAdd(&g_cursor[d], 1);
        g_col[p] = src[e];
    }
}

// ---------------- mean aggregation: warp per node, lane = one float4, 4-way unroll ----------------
// Emits mean packed as bf16 hi|lo per value (bit-identical to the GEMM's former converter).
__device__ __forceinline__ uint32_t pack_hilo(float v) {
    __nv_bfloat16 h = __float2bfloat16(v);
    float r = v - __bfloat162float(h);
    __nv_bfloat16 l = __float2bfloat16(r);
    return (uint32_t)__bfloat16_as_ushort(h) | ((uint32_t)__bfloat16_as_ushort(l) << 16);
}

__global__ void k_aggregate(const float* __restrict__ feat, uint32_t* __restrict__ mean) {
    int warp = (blockIdx.x * blockDim.x + threadIdx.x) >> 5;
    int lane = threadIdx.x & 31;
    if (warp >= NN) return;
    int s = g_rowptr[warp];
    int e = g_rowptr[warp + 1];
    float4 acc = make_float4(0.f, 0.f, 0.f, 0.f);
    const float4* f4 = (const float4*)feat;
    int i = s;
    for (; i + 4 <= e; i += 4) {
        int c0 = __ldg(&g_col[i]);
        int c1 = __ldg(&g_col[i + 1]);
        int c2 = __ldg(&g_col[i + 2]);
        int c3 = __ldg(&g_col[i + 3]);
        float4 v0 = __ldg(&f4[c0 * 32 + lane]);
        float4 v1 = __ldg(&f4[c1 * 32 + lane]);
        float4 v2 = __ldg(&f4[c2 * 32 + lane]);
        float4 v3 = __ldg(&f4[c3 * 32 + lane]);
        acc.x += v0.x + v1.x + v2.x + v3.x;
        acc.y += v0.y + v1.y + v2.y + v3.y;
        acc.z += v0.z + v1.z + v2.z + v3.z;
        acc.w += v0.w + v1.w + v2.w + v3.w;
    }
    for (; i < e; i++) {
        int c = __ldg(&g_col[i]);
        float4 v = __ldg(&f4[c * 32 + lane]);
        acc.x += v.x; acc.y += v.y; acc.z += v.z; acc.w += v.w;
    }
    int cnt = e - s;
    float inv = 1.0f / (float)(cnt > 0 ? cnt : 1);
    uint4 o;
    o.x = pack_hilo(acc.x * inv);
    o.y = pack_hilo(acc.y * inv);
    o.z = pack_hilo(acc.z * inv);
    o.w = pack_hilo(acc.w * inv);
    ((uint4*)mean)[warp * 32 + lane] = o;
}

// ---------------- tensor-core SAGE GEMM ----------------
// out[128 rows tile][128] = relu([mean|feat] @ W + bias), K = 256.
// 3-term bf16 split: D = Ah*Bh + Ah*Bl + Al*Bh (fp32 accumulate).
// Chunks 0,1 (mean): packed bf16 hi/lo in global -> PRMT-split staging.
// Chunks 2,3 (feat): fp32 -> cvt staging (as before).
#define APITCH 36

__device__ __forceinline__ void mma_bf16(float* c, const uint32_t* a,
                                         uint32_t b0, uint32_t b1) {
    asm("mma.sync.aligned.m16n8k16.row.col.f32.bf16.bf16.f32 "
        "{%0,%1,%2,%3}, {%4,%5,%6,%7}, {%8,%9}, {%0,%1,%2,%3};"
        : "+f"(c[0]), "+f"(c[1]), "+f"(c[2]), "+f"(c[3])
        : "r"(a[0]), "r"(a[1]), "r"(a[2]), "r"(a[3]), "r"(b0), "r"(b1));
}

__global__ __launch_bounds__(256)
void k_gemm_mma(const uint32_t* __restrict__ pmean, const float* __restrict__ Afeat,
                const uint4* __restrict__ Wfrag, const float* __restrict__ bias,
                float* __restrict__ out) {
    __shared__ uint32_t sAhi[128 * APITCH];
    __shared__ uint32_t sAlo[128 * APITCH];

    const int tid  = threadIdx.x;
    const int wid  = tid >> 5;
    const int lane = tid & 31;
    const int wr = wid >> 2;           // 0..1
    const int wc = wid & 3;            // 0..3
    const int row0 = blockIdx.x * 128;

    float acc[4][4][4];
#pragma unroll
    for (int i = 0; i < 4; i++)
#pragma unroll
        for (int j = 0; j < 4; j++)
#pragma unroll
            for (int r = 0; r < 4; r++) acc[i][j][r] = 0.f;

    for (int chunk = 0; chunk < 4; chunk++) {
        const int kb = (chunk & 1) * 64;

        // ---- stage A chunk: 128 rows x 64 k -> bf16 hi/lo smem images ----
        {
            int r = tid >> 1;
            int half = tid & 1;
            int grow = row0 + r;
            if (chunk < 2) {
                // mean: packed bf16 hi|lo words -> PRMT split
                const uint4* Ag = (const uint4*)(pmean + (size_t)grow * D + kb);
#pragma unroll
                for (int q = 0; q < 8; q++) {
                    uint4 p = make_uint4(0u, 0u, 0u, 0u);
                    if (grow < NN) p = __ldg(&Ag[half * 8 + q]);
                    uint2 hv, lv;
                    hv.x = __byte_perm(p.x, p.y, 0x5410);
                    hv.y = __byte_perm(p.z, p.w, 0x5410);
                    lv.x = __byte_perm(p.x, p.y, 0x7632);
                    lv.y = __byte_perm(p.z, p.w, 0x7632);
                    int c = half * 16 + q * 2;
                    *(uint2*)&sAhi[r * APITCH + c] = hv;
                    *(uint2*)&sAlo[r * APITCH + c] = lv;
                }
            } else {
                // feat: fp32 -> cvt split
                const float4* Ag = (const float4*)(Afeat + (size_t)grow * D + kb);
#pragma unroll
                for (int q = 0; q < 8; q++) {
                    float4 v = make_float4(0.f, 0.f, 0.f, 0.f);
                    if (grow < NN) v = __ldg(&Ag[half * 8 + q]);
                    __nv_bfloat16 hx = __float2bfloat16(v.x);
                    __nv_bfloat16 hy = __float2bfloat16(v.y);
                    __nv_bfloat16 hz = __float2bfloat16(v.z);
                    __nv_bfloat16 hw = __float2bfloat16(v.w);
                    uint2 hv, lv;
                    hv.x = (uint32_t)__bfloat16_as_ushort(hx) |
                           ((uint32_t)__bfloat16_as_ushort(hy) << 16);
                    hv.y = (uint32_t)__bfloat16_as_ushort(hz) |
                           ((uint32_t)__bfloat16_as_ushort(hw) << 16);
                    __nv_bfloat16 lx = __float2bfloat16(v.x - __bfloat162float(hx));
                    __nv_bfloat16 ly = __float2bfloat16(v.y - __bfloat162float(hy));
                    __nv_bfloat16 lz = __float2bfloat16(v.z - __bfloat162float(hz));
                    __nv_bfloat16 lw = __float2bfloat16(v.w - __bfloat162float(hw));
                    lv.x = (uint32_t)__bfloat16_as_ushort(lx) |
                           ((uint32_t)__bfloat16_as_ushort(ly) << 16);
                    lv.y = (uint32_t)__bfloat16_as_ushort(lz) |
                           ((uint32_t)__bfloat16_as_ushort(lw) << 16);
                    int c = half * 16 + q * 2;
                    *(uint2*)&sAhi[r * APITCH + c] = hv;
                    *(uint2*)&sAlo[r * APITCH + c] = lv;
                }
            }
        }
        __syncthreads();

        // ---- mma over 4 k-steps of 16 ----
#pragma unroll
        for (int t = 0; t < 4; t++) {
            uint4 B[4];
#pragma unroll
            for (int j = 0; j < 4; j++)
                B[j] = __ldg(&Wfrag[(((chunk * 4 + t) * 16) + (wc * 4 + j)) * 32 + lane]);

            const int rb = wr * 64 + (lane >> 2);
            const int cw = t * 8 + (lane & 3);
#pragma unroll
            for (int i = 0; i < 4; i++) {
                int base = (rb + i * 16) * APITCH;
                uint32_t ah[4], al[4];
                ah[0] = sAhi[base + cw];
                ah[1] = sAhi[base + 8 * APITCH + cw];
                ah[2] = sAhi[base + cw + 4];
                ah[3] = sAhi[base + 8 * APITCH + cw + 4];
                al[0] = sAlo[base + cw];
                al[1] = sAlo[base + 8 * APITCH + cw];
                al[2] = sAlo[base + cw + 4];
                al[3] = sAlo[base + 8 * APITCH + cw + 4];
#pragma unroll
                for (int j = 0; j < 4; j++) {
                    mma_bf16(acc[i][j], ah, B[j].x, B[j].y);  // Ah*Bh
                    mma_bf16(acc[i][j], ah, B[j].z, B[j].w);  // Ah*Bl
                    mma_bf16(acc[i][j], al, B[j].x, B[j].y);  // Al*Bh
                }
            }
        }
        __syncthreads();
    }

    // ---- epilogue: bias + relu, float2 stores ----
#pragma unroll
    for (int j = 0; j < 4; j++) {
        int col = wc * 32 + j * 8 + (lane & 3) * 2;
        float b0 = __ldg(&bias[col]);
        float b1 = __ldg(&bias[col + 1]);
#pragma unroll
        for (int i = 0; i < 4; i++) {
            int row = row0 + wr * 64 + i * 16 + (lane >> 2);
            if (row < NN) {
                float2 v0;
                v0.x = fmaxf(acc[i][j][0] + b0, 0.f);
                v0.y = fmaxf(acc[i][j][1] + b1, 0.f);
                *(float2*)(out + (size_t)row * D + col) = v0;
            }
            if (row + 8 < NN) {
                float2 v1;
                v1.x = fmaxf(acc[i][j][2] + b0, 0.f);
                v1.y = fmaxf(acc[i][j][3] + b1, 0.f);
                *(float2*)(out + (size_t)(row + 8) * D + col) = v1;
            }
        }
    }
}

// ---------------- fully fused tail: max-pool -> mlp1 -> mlp2 -> head ----------------
__global__ void k_tail(const float* __restrict__ h, const float* __restrict__ x,
                       const float* __restrict__ W1, const float* __restrict__ b1,
                       const float* __restrict__ W2, const float* __restrict__ b2,
                       const float* __restrict__ Wsm, const float* __restrict__ bsm,
                       const float* __restrict__ Wnews, const float* __restrict__ bnews,
                       const float* __restrict__ Wcat, const float* __restrict__ bcat,
                       float* __restrict__ out) {
    __shared__ float pool[128];
    __shared__ float pmax[256];
    __shared__ float f1s[256];
    __shared__ float f2s[128];
    __shared__ float xroot[128];
    int g = blockIdx.x;
    int tid = threadIdx.x;
    int col = tid & 127, half = tid >> 7;
    int s = g_root[g], e = g_root[g + 1];
    float m = -3.4e38f;
    for (int n = s + half; n < e; n += 2) m = fmaxf(m, h[(size_t)n * D + col]);
    pmax[tid] = m;
    __syncthreads();
    if (tid < 128) {
        pool[tid] = fmaxf(pmax[tid], pmax[tid + 128]);
        xroot[tid] = x[(size_t)s * D + tid];
    }
    __syncthreads();
    float a1 = b1[tid];
#pragma unroll 16
    for (int k = 0; k < 128; k++) a1 += pool[k] * W1[k * 256 + tid];
    f1s[tid] = fmaxf(a1, 0.f);
    __syncthreads();
    if (tid < 128) {
        float a2 = b2[tid];
#pragma unroll 16
        for (int k = 0; k < 256; k++) a2 += f1s[k] * W2[k * 128 + tid];
        f2s[tid] = fmaxf(a2, 0.f);
    }
    __syncthreads();
    if (tid < 32) {
        int kb = tid * 4;
        float s0 = 0.f, s1 = 0.f, n0 = 0.f, n1 = 0.f;
#pragma unroll
        for (int t = 0; t < 4; t++) {
            float fv = f2s[kb + t];
            float xv = xroot[kb + t];
            s0 += fv * Wsm[(kb + t) * 2 + 0];
            s1 += fv * Wsm[(kb + t) * 2 + 1];
            n0 += xv * Wnews[(kb + t) * 2 + 0];
            n1 += xv * Wnews[(kb + t) * 2 + 1];
        }
#pragma unroll
        for (int off = 16; off > 0; off >>= 1) {
            s0 += __shfl_down_sync(0xffffffffu, s0, off);
            s1 += __shfl_down_sync(0xffffffffu, s1, off);
            n0 += __shfl_down_sync(0xffffffffu, n0, off);
            n1 += __shfl_down_sync(0xffffffffu, n1, off);
        }
        if (tid == 0) {
            float h0 = fmaxf(s0 + bsm[0], 0.f);
            float h1 = fmaxf(s1 + bsm[1], 0.f);
            float m0 = fmaxf(n0 + bnews[0], 0.f);
            float m1 = fmaxf(n1 + bnews[1], 0.f);
            float z = h0 * Wcat[0] + h1 * Wcat[1] + m0 * Wcat[2] + m1 * Wcat[3] + bcat[0];
            out[g] = 1.0f / (1.0f + expf(-z));
        }
    }
}

// ---------------- launch ----------------
extern "C" void kernel_launch(void* const* d_in, const int* in_sizes, int n_in,
                              void* d_out, int out_size) {
    const float* x     = (const float*)d_in[0];
    const int*   ei    = (const int*)d_in[1];
    const int*   src   = ei;
    const int*   dst   = ei + EE;
    const int*   batch = (const int*)d_in[2];
    const float* Wl1 = (const float*)d_in[3];
    const float* Wr1 = (const float*)d_in[4];
    const float* bl1 = (const float*)d_in[5];
    const float* Wl2 = (const float*)d_in[6];
    const float* Wr2 = (const float*)d_in[7];
    const float* bl2 = (const float*)d_in[8];
    const float* Wl3 = (const float*)d_in[9];
    const float* Wr3 = (const float*)d_in[10];
    const float* bl3 = (const float*)d_in[11];
    const float* W_f1 = (const float*)d_in[12];
    const float* b_f1 = (const float*)d_in[13];
    const float* W_f2 = (const float*)d_in[14];
    const float* b_f2 = (const float*)d_in[15];
    const float* W_sm = (const float*)d_in[16];
    const float* b_sm = (const float*)d_in[17];
    const float* W_news = (const float*)d_in[18];
    const float* b_news = (const float*)d_in[19];
    const float* W_cat = (const float*)d_in[20];
    const float* b_cat = (const float*)d_in[21];
    float* out = (float*)d_out;

    uint32_t* mean;
    float *h1, *h2;
    uint4* wfrag;
    cudaGetSymbolAddress((void**)&mean, g_mean);
    cudaGetSymbolAddress((void**)&h1, g_h1);
    cudaGetSymbolAddress((void**)&h2, g_h2);
    cudaGetSymbolAddress((void**)&wfrag, g_Wfrag);

    const int TB = 256;
    const int gN = (NN + TB - 1) / TB;
    const int gE = (EE + TB - 1) / TB;

    // CSR build + roots + weight fragment prep
    k_initprep<<<gN, TB>>>(batch, Wl1, Wr1, Wl2, Wr2, Wl3, Wr3);
    k_hist<<<gE, TB>>>(dst);
    k_scan_one<<<SCAN_BLKS, 1024>>>();
    k_fill<<<gE, TB>>>(src, dst);

    const int gAgg = (NN * 32 + TB - 1) / TB;  // warp per node
    const int gGemm = (NN + 127) / 128;        // 391

    // layer 1: x -> h1
    k_aggregate<<<gAgg, TB>>>(x, mean);
    k_gemm_mma<<<gGemm, TB>>>(mean, x, wfrag, bl1, h1);
    // layer 2: h1 -> h2
    k_aggregate<<<gAgg, TB>>>(h1, mean);
    k_gemm_mma<<<gGemm, TB>>>(mean, h1, wfrag + 8192, bl2, h2);
    // layer 3: h2 -> h1
    k_aggregate<<<gAgg, TB>>>(h2, mean);
    k_gemm_mma<<<gGemm, TB>>>(mean, h2, wfrag + 16384, bl3, h1);

    // fused tail
    k_tail<<<BG, TB>>>(h1, x, W_f1, b_f1, W_f2, b_f2, W_sm, b_sm,
                       W_news, b_news, W_cat, b_cat, out);
}